// round 1
// baseline (speedup 1.0000x reference)
#include <cuda_runtime.h>
#include <math.h>

#define B_ 8
#define H_ 128
#define W_ 256
#define C_ 64
#define F_ 64
#define NPIX (B_*H_*W_)

// Scratch for conv outputs (allocation-free rule: __device__ globals)
__device__ float g_q[(size_t)NPIX * F_];
__device__ float g_k[(size_t)NPIX * F_];
__device__ float g_v[(size_t)NPIX * F_];

#define XS_LD 68
#define WS_LD 192
#define CONV_SMEM ((64*XS_LD + 64*WS_LD) * 4)          // 66560 B
#define ATTN_SMEM ((64*68 + 64*68 + 64*64) * 4)        // 51200 B

// ---------------------------------------------------------------------------
// Fused QKV dilated conv: 3x3, dilation 2, SAME pad, stride 1.
// grid (W_/64, B_*H_), 256 threads. Block tile: 64 w  x  192 f (q|k|v).
// Micro-tile per thread: 4 w x (3 convs x 4 f).
// ---------------------------------------------------------------------------
__global__ __launch_bounds__(256) void conv_qkv_kernel(
    const float* __restrict__ X,
    const float* __restrict__ Wq, const float* __restrict__ bq,
    const float* __restrict__ Wk, const float* __restrict__ bk,
    const float* __restrict__ Wv, const float* __restrict__ bv)
{
    extern __shared__ float sm[];
    float* Xs = sm;                  // [64 c][68]   (c-major, w inner, padded)
    float* Ws = sm + 64 * XS_LD;     // [64 c][192]  (q:0-63, k:64-127, v:128-191)

    const int t  = threadIdx.x;
    const int bh = blockIdx.y;
    const int b  = bh / H_;
    const int h  = bh % H_;
    const int w0 = blockIdx.x * 64;
    const int tw = t >> 4;           // 0..15 -> w group
    const int tf = t & 15;           // 0..15 -> f group

    float accq[4][4], acck[4][4], accv[4][4];
    #pragma unroll
    for (int i = 0; i < 4; i++)
        #pragma unroll
        for (int j = 0; j < 4; j++) { accq[i][j]=0.f; acck[i][j]=0.f; accv[i][j]=0.f; }

    #pragma unroll 1
    for (int kh = 0; kh < 3; kh++) {
        const int hh = h + (kh - 1) * 2;
        const bool hok = (hh >= 0) && (hh < H_);
        const float* xrow = X + ((size_t)(b * H_ + hh) * W_) * C_;
        #pragma unroll 1
        for (int kw = 0; kw < 3; kw++) {
            const int dw = (kw - 1) * 2;
            __syncthreads();   // previous GEMM done reading smem

            // ---- load X tile: Xs[c][w], zero-padded at borders ----
            #pragma unroll
            for (int i = 0; i < 4; i++) {
                int idx = t + i * 256;      // 0..1023
                int wl  = idx >> 4;         // 0..63
                int c4  = idx & 15;         // 0..15 (float4 group of c)
                int ww  = w0 + wl + dw;
                float4 xv = make_float4(0.f, 0.f, 0.f, 0.f);
                if (hok && (unsigned)ww < (unsigned)W_)
                    xv = *reinterpret_cast<const float4*>(xrow + (size_t)ww * C_ + c4 * 4);
                Xs[(c4*4+0)*XS_LD + wl] = xv.x;
                Xs[(c4*4+1)*XS_LD + wl] = xv.y;
                Xs[(c4*4+2)*XS_LD + wl] = xv.z;
                Xs[(c4*4+3)*XS_LD + wl] = xv.w;
            }
            // ---- load weight tiles for this tap: 64c x 64f x 3 ----
            const int tapoff = (kh * 3 + kw) * C_ * F_;
            #pragma unroll
            for (int i = 0; i < 4; i++) {
                int idx = t + i * 256;
                int c   = idx >> 4;
                int f4  = idx & 15;
                float4 wv;
                wv = *reinterpret_cast<const float4*>(Wq + tapoff + c * F_ + f4 * 4);
                *reinterpret_cast<float4*>(Ws + c * WS_LD +   0 + f4 * 4) = wv;
                wv = *reinterpret_cast<const float4*>(Wk + tapoff + c * F_ + f4 * 4);
                *reinterpret_cast<float4*>(Ws + c * WS_LD +  64 + f4 * 4) = wv;
                wv = *reinterpret_cast<const float4*>(Wv + tapoff + c * F_ + f4 * 4);
                *reinterpret_cast<float4*>(Ws + c * WS_LD + 128 + f4 * 4) = wv;
            }
            __syncthreads();

            // ---- GEMM over c ----
            #pragma unroll 8
            for (int c = 0; c < 64; c++) {
                float4 xv = *reinterpret_cast<const float4*>(Xs + c * XS_LD + tw * 4);
                float4 aq = *reinterpret_cast<const float4*>(Ws + c * WS_LD +   0 + tf * 4);
                float4 ak = *reinterpret_cast<const float4*>(Ws + c * WS_LD +  64 + tf * 4);
                float4 av = *reinterpret_cast<const float4*>(Ws + c * WS_LD + 128 + tf * 4);
                float xr[4] = {xv.x, xv.y, xv.z, xv.w};
                float qr[4] = {aq.x, aq.y, aq.z, aq.w};
                float kr[4] = {ak.x, ak.y, ak.z, ak.w};
                float vr[4] = {av.x, av.y, av.z, av.w};
                #pragma unroll
                for (int i = 0; i < 4; i++) {
                    #pragma unroll
                    for (int j = 0; j < 4; j++) {
                        accq[i][j] = fmaf(xr[i], qr[j], accq[i][j]);
                        acck[i][j] = fmaf(xr[i], kr[j], acck[i][j]);
                        accv[i][j] = fmaf(xr[i], vr[j], accv[i][j]);
                    }
                }
            }
        }
    }

    // ---- epilogue: + bias, coalesced float4 stores ----
    float4 bq4 = *reinterpret_cast<const float4*>(bq + tf * 4);
    float4 bk4 = *reinterpret_cast<const float4*>(bk + tf * 4);
    float4 bv4 = *reinterpret_cast<const float4*>(bv + tf * 4);
    #pragma unroll
    for (int i = 0; i < 4; i++) {
        size_t pix = (size_t)bh * W_ + w0 + tw * 4 + i;
        size_t off = pix * F_ + tf * 4;
        float4 r;
        r.x = accq[i][0] + bq4.x; r.y = accq[i][1] + bq4.y;
        r.z = accq[i][2] + bq4.z; r.w = accq[i][3] + bq4.w;
        *reinterpret_cast<float4*>(g_q + off) = r;
        r.x = acck[i][0] + bk4.x; r.y = acck[i][1] + bk4.y;
        r.z = acck[i][2] + bk4.z; r.w = acck[i][3] + bk4.w;
        *reinterpret_cast<float4*>(g_k + off) = r;
        r.x = accv[i][0] + bv4.x; r.y = accv[i][1] + bv4.y;
        r.z = accv[i][2] + bv4.z; r.w = accv[i][3] + bv4.w;
        *reinterpret_cast<float4*>(g_v + off) = r;
    }
}

// ---------------------------------------------------------------------------
// Flash attention along W per (b,h). grid (W_/64, B_*H_), 256 threads.
// Q tile 64 rows; KV tiles of 64; online softmax; no score scaling.
// ---------------------------------------------------------------------------
__global__ __launch_bounds__(256) void attn_kernel(float* __restrict__ out)
{
    extern __shared__ float sm[];
    float* Qs  = sm;               // [64 c][68]  Qs[c][i]
    float* KPs = sm + 64 * 68;     // [64][68]    Ks[c][j], then Ps[j][i]
    float* Vs  = sm + 2 * 64 * 68; // [64 j][64 f]

    const int t  = threadIdx.x;
    const int tq = t >> 4;         // 0..15
    const int tf = t & 15;         // 0..15 (= tk for S-gemm)
    const int bh = blockIdx.y;
    const int q0 = blockIdx.x * 64;

    const float* qb = g_q + (size_t)bh * W_ * F_;
    const float* kb = g_k + (size_t)bh * W_ * F_;
    const float* vb = g_v + (size_t)bh * W_ * F_;

    // ---- load Q tile (transposed to c-major) ----
    #pragma unroll
    for (int i = 0; i < 4; i++) {
        int idx = t + i * 256;
        int il  = idx >> 4;
        int c4  = idx & 15;
        float4 qv = *reinterpret_cast<const float4*>(qb + (size_t)(q0 + il) * F_ + c4 * 4);
        Qs[(c4*4+0)*68 + il] = qv.x;
        Qs[(c4*4+1)*68 + il] = qv.y;
        Qs[(c4*4+2)*68 + il] = qv.z;
        Qs[(c4*4+3)*68 + il] = qv.w;
    }

    float o[4][4];
    float m[4], l[4];
    #pragma unroll
    for (int i = 0; i < 4; i++) {
        m[i] = -INFINITY; l[i] = 0.f;
        #pragma unroll
        for (int j = 0; j < 4; j++) o[i][j] = 0.f;
    }
    __syncthreads();

    #pragma unroll 1
    for (int k0 = 0; k0 < W_; k0 += 64) {
        // ---- load K (transposed) and V tiles ----
        #pragma unroll
        for (int i = 0; i < 4; i++) {
            int idx = t + i * 256;
            int jl  = idx >> 4;
            int c4  = idx & 15;
            float4 kv = *reinterpret_cast<const float4*>(kb + (size_t)(k0 + jl) * F_ + c4 * 4);
            KPs[(c4*4+0)*68 + jl] = kv.x;
            KPs[(c4*4+1)*68 + jl] = kv.y;
            KPs[(c4*4+2)*68 + jl] = kv.z;
            KPs[(c4*4+3)*68 + jl] = kv.w;
            float4 vv = *reinterpret_cast<const float4*>(vb + (size_t)(k0 + jl) * F_ + c4 * 4);
            *reinterpret_cast<float4*>(Vs + jl * 64 + c4 * 4) = vv;
        }
        __syncthreads();

        // ---- S = Q @ K^T (64x64 tile, 4x4 micro) ----
        float s[4][4];
        #pragma unroll
        for (int i = 0; i < 4; i++)
            #pragma unroll
            for (int j = 0; j < 4; j++) s[i][j] = 0.f;
        #pragma unroll 8
        for (int c = 0; c < 64; c++) {
            float4 qv = *reinterpret_cast<const float4*>(Qs  + c * 68 + tq * 4);
            float4 kv = *reinterpret_cast<const float4*>(KPs + c * 68 + tf * 4);
            float qr[4] = {qv.x, qv.y, qv.z, qv.w};
            float kr[4] = {kv.x, kv.y, kv.z, kv.w};
            #pragma unroll
            for (int i = 0; i < 4; i++)
                #pragma unroll
                for (int j = 0; j < 4; j++)
                    s[i][j] = fmaf(qr[i], kr[j], s[i][j]);
        }

        // ---- online softmax (row reductions across 16 tf-lanes) ----
        float p[4][4];
        #pragma unroll
        for (int i = 0; i < 4; i++) {
            float mm = fmaxf(fmaxf(s[i][0], s[i][1]), fmaxf(s[i][2], s[i][3]));
            #pragma unroll
            for (int d = 1; d < 16; d <<= 1)
                mm = fmaxf(mm, __shfl_xor_sync(0xffffffffu, mm, d));
            float mnew = fmaxf(m[i], mm);
            float sc = __expf(m[i] - mnew);   // 0 on first tile (m=-inf)
            m[i] = mnew;
            float ls = 0.f;
            #pragma unroll
            for (int j = 0; j < 4; j++) {
                p[i][j] = __expf(s[i][j] - mnew);
                ls += p[i][j];
            }
            #pragma unroll
            for (int d = 1; d < 16; d <<= 1)
                ls += __shfl_xor_sync(0xffffffffu, ls, d);
            l[i] = l[i] * sc + ls;
            #pragma unroll
            for (int j = 0; j < 4; j++) o[i][j] *= sc;
        }

        __syncthreads();   // done reading KPs as K
        // ---- stage P transposed: Ps[j][i] ----
        #pragma unroll
        for (int i = 0; i < 4; i++)
            #pragma unroll
            for (int j = 0; j < 4; j++)
                KPs[(tf*4 + j) * 68 + tq*4 + i] = p[i][j];
        __syncthreads();

        // ---- O += P @ V ----
        #pragma unroll 8
        for (int j = 0; j < 64; j++) {
            float4 pv = *reinterpret_cast<const float4*>(KPs + j * 68 + tq * 4);
            float4 vv = *reinterpret_cast<const float4*>(Vs  + j * 64 + tf * 4);
            float pr[4] = {pv.x, pv.y, pv.z, pv.w};
            float vr[4] = {vv.x, vv.y, vv.z, vv.w};
            #pragma unroll
            for (int i = 0; i < 4; i++)
                #pragma unroll
                for (int f = 0; f < 4; f++)
                    o[i][f] = fmaf(pr[i], vr[f], o[i][f]);
        }
        __syncthreads();   // before next tile overwrites KPs/Vs
    }

    // ---- epilogue: normalize and store ----
    #pragma unroll
    for (int i = 0; i < 4; i++) {
        float inv = 1.0f / l[i];
        size_t off = ((size_t)bh * W_ + q0 + tq * 4 + i) * F_ + tf * 4;
        float4 r;
        r.x = o[i][0] * inv; r.y = o[i][1] * inv;
        r.z = o[i][2] * inv; r.w = o[i][3] * inv;
        *reinterpret_cast<float4*>(out + off) = r;
    }
}

// ---------------------------------------------------------------------------
extern "C" void kernel_launch(void* const* d_in, const int* in_sizes, int n_in,
                              void* d_out, int out_size)
{
    const float* X  = (const float*)d_in[0];
    const float* Wq = (const float*)d_in[1];
    const float* bq = (const float*)d_in[2];
    const float* Wk = (const float*)d_in[3];
    const float* bk = (const float*)d_in[4];
    const float* Wv = (const float*)d_in[5];
    const float* bv = (const float*)d_in[6];
    float* out = (float*)d_out;

    cudaFuncSetAttribute(conv_qkv_kernel,
                         cudaFuncAttributeMaxDynamicSharedMemorySize, CONV_SMEM);
    cudaFuncSetAttribute(attn_kernel,
                         cudaFuncAttributeMaxDynamicSharedMemorySize, ATTN_SMEM);

    dim3 cgrid(W_ / 64, B_ * H_);
    conv_qkv_kernel<<<cgrid, 256, CONV_SMEM>>>(X, Wq, bq, Wk, bk, Wv, bv);

    dim3 agrid(W_ / 64, B_ * H_);
    attn_kernel<<<agrid, 256, ATTN_SMEM>>>(out);
}

// round 2
// speedup vs baseline: 1.0384x; 1.0384x over previous
#include <cuda_runtime.h>
#include <math.h>

#define B_ 8
#define H_ 128
#define W_ 256
#define C_ 64
#define F_ 64
#define NPIX (B_*H_*W_)

// Scratch for conv outputs (allocation-free rule: __device__ globals)
__device__ float g_q[(size_t)NPIX * F_];
__device__ float g_k[(size_t)NPIX * F_];
__device__ float g_v[(size_t)NPIX * F_];

#define XS_LD 68                         // floats per Xs row (64 used + pad, odd granule stride)
#define WS_LD 192
#define CONV_SMEM ((68*XS_LD + 64*WS_LD) * 4)   // 18,496 + 49,152 = 67,648 B
#define ATTN_SMEM ((64*68 + 64*68 + 64*64) * 4) // 51,200 B

// ---------------------------------------------------------------------------
// Fused QKV dilated conv: 3x3, dilation 2, SAME pad, stride 1.
// grid (W_/64, B_*H_), 256 threads. Block tile: 64 w x 192 f (q|k|v).
// X kept ROW-MAJOR [w][c] in smem (conflict-free staging + reads),
// staged once per kh with a 68-wide window; kw taps read shifted rows.
// Micro-tile 4w x 12f, c-loop unrolled by 4.
// ---------------------------------------------------------------------------
__global__ __launch_bounds__(256, 2) void conv_qkv_kernel(
    const float* __restrict__ X,
    const float* __restrict__ Wq, const float* __restrict__ bq,
    const float* __restrict__ Wk, const float* __restrict__ bk,
    const float* __restrict__ Wv, const float* __restrict__ bv)
{
    extern __shared__ float sm[];
    float* Xs = sm;                  // [68 rows][XS_LD]  row-major: Xs[wl][c]
    float* Ws = sm + 68 * XS_LD;     // [64 c][192 f]     (q:0-63, k:64-127, v:128-191)

    const int t  = threadIdx.x;
    const int bh = blockIdx.y;
    const int b  = bh / H_;
    const int h  = bh % H_;
    const int w0 = blockIdx.x * 64;
    const int tw = t >> 4;           // 0..15 -> w group (4 rows)
    const int tf = t & 15;           // 0..15 -> f group (4 f per conv)

    float accq[4][4], acck[4][4], accv[4][4];
    #pragma unroll
    for (int i = 0; i < 4; i++)
        #pragma unroll
        for (int j = 0; j < 4; j++) { accq[i][j]=0.f; acck[i][j]=0.f; accv[i][j]=0.f; }

    #pragma unroll 1
    for (int kh = 0; kh < 3; kh++) {
        const int hh = h + (kh - 1) * 2;
        const bool hok = (hh >= 0) && (hh < H_);
        const float* xrow = X + ((size_t)(b * H_ + hh) * W_) * C_;

        __syncthreads();   // prior tap's GEMM done reading Xs and Ws

        // ---- stage X window [w0-2, w0+66) row-major, zero padded ----
        // 68 rows x 16 float4 granules = 1088 granules
        for (int idx = t; idx < 68 * 16; idx += 256) {
            int wl = idx >> 4;
            int c4 = idx & 15;
            int ww = w0 - 2 + wl;
            float4 xv = make_float4(0.f, 0.f, 0.f, 0.f);
            if (hok && (unsigned)ww < (unsigned)W_)
                xv = *reinterpret_cast<const float4*>(xrow + (size_t)ww * C_ + c4 * 4);
            *reinterpret_cast<float4*>(Xs + wl * XS_LD + c4 * 4) = xv;
        }

        #pragma unroll 1
        for (int kw = 0; kw < 3; kw++) {
            if (kw) __syncthreads();   // prior GEMM done reading Ws

            // ---- stage weights for this tap: 64c x 64f x 3 ----
            const int tapoff = (kh * 3 + kw) * C_ * F_;
            #pragma unroll
            for (int i = 0; i < 4; i++) {
                int idx = t + i * 256;
                int c   = idx >> 4;
                int f4  = idx & 15;
                float4 wv;
                wv = *reinterpret_cast<const float4*>(Wq + tapoff + c * F_ + f4 * 4);
                *reinterpret_cast<float4*>(Ws + c * WS_LD +   0 + f4 * 4) = wv;
                wv = *reinterpret_cast<const float4*>(Wk + tapoff + c * F_ + f4 * 4);
                *reinterpret_cast<float4*>(Ws + c * WS_LD +  64 + f4 * 4) = wv;
                wv = *reinterpret_cast<const float4*>(Wv + tapoff + c * F_ + f4 * 4);
                *reinterpret_cast<float4*>(Ws + c * WS_LD + 128 + f4 * 4) = wv;
            }
            __syncthreads();

            // ---- GEMM over c, unrolled by 4 ----
            const int rbase = tw * 4 + kw * 2;   // row in Xs = wl + dw + 2
            #pragma unroll 4
            for (int c0 = 0; c0 < 64; c0 += 4) {
                float4 xv[4];
                #pragma unroll
                for (int i = 0; i < 4; i++)
                    xv[i] = *reinterpret_cast<const float4*>(Xs + (rbase + i) * XS_LD + c0);
                #pragma unroll
                for (int cc = 0; cc < 4; cc++) {
                    const float* wr = Ws + (c0 + cc) * WS_LD + tf * 4;
                    float4 aq = *reinterpret_cast<const float4*>(wr +   0);
                    float4 ak = *reinterpret_cast<const float4*>(wr +  64);
                    float4 av = *reinterpret_cast<const float4*>(wr + 128);
                    float qr[4] = {aq.x, aq.y, aq.z, aq.w};
                    float kr[4] = {ak.x, ak.y, ak.z, ak.w};
                    float vr[4] = {av.x, av.y, av.z, av.w};
                    #pragma unroll
                    for (int i = 0; i < 4; i++) {
                        float x = reinterpret_cast<const float*>(&xv[i])[cc];
                        #pragma unroll
                        for (int j = 0; j < 4; j++) {
                            accq[i][j] = fmaf(x, qr[j], accq[i][j]);
                            acck[i][j] = fmaf(x, kr[j], acck[i][j]);
                            accv[i][j] = fmaf(x, vr[j], accv[i][j]);
                        }
                    }
                }
            }
        }
    }

    // ---- epilogue: + bias, coalesced float4 stores ----
    float4 bq4 = *reinterpret_cast<const float4*>(bq + tf * 4);
    float4 bk4 = *reinterpret_cast<const float4*>(bk + tf * 4);
    float4 bv4 = *reinterpret_cast<const float4*>(bv + tf * 4);
    #pragma unroll
    for (int i = 0; i < 4; i++) {
        size_t pix = (size_t)bh * W_ + w0 + tw * 4 + i;
        size_t off = pix * F_ + tf * 4;
        float4 r;
        r.x = accq[i][0] + bq4.x; r.y = accq[i][1] + bq4.y;
        r.z = accq[i][2] + bq4.z; r.w = accq[i][3] + bq4.w;
        *reinterpret_cast<float4*>(g_q + off) = r;
        r.x = acck[i][0] + bk4.x; r.y = acck[i][1] + bk4.y;
        r.z = acck[i][2] + bk4.z; r.w = acck[i][3] + bk4.w;
        *reinterpret_cast<float4*>(g_k + off) = r;
        r.x = accv[i][0] + bv4.x; r.y = accv[i][1] + bv4.y;
        r.z = accv[i][2] + bv4.z; r.w = accv[i][3] + bv4.w;
        *reinterpret_cast<float4*>(g_v + off) = r;
    }
}

// ---------------------------------------------------------------------------
// Flash attention along W per (b,h). grid (W_/64, B_*H_), 256 threads.
// Q row-major in smem; K c-major; P staged ROW-MAJOR with float4 stores
// (conflict-free); both GEMMs unrolled by 4 over the reduction dim.
// ---------------------------------------------------------------------------
__global__ __launch_bounds__(256) void attn_kernel(float* __restrict__ out)
{
    extern __shared__ float sm[];
    float* Qs = sm;                // [64 q][68]  row-major Qs[i][c]
    float* KP = sm + 64 * 68;      // [64 c][68]  Ks[c][j]; then P[64 q][68 k]
    float* Vs = sm + 2 * 64 * 68;  // [64 k][64 f]

    const int t  = threadIdx.x;
    const int tq = t >> 4;         // 0..15
    const int tf = t & 15;         // 0..15
    const int bh = blockIdx.y;
    const int q0 = blockIdx.x * 64;

    const float* qb = g_q + (size_t)bh * W_ * F_;
    const float* kb = g_k + (size_t)bh * W_ * F_;
    const float* vb = g_v + (size_t)bh * W_ * F_;

    // ---- load Q tile, row-major direct copy (conflict-free) ----
    #pragma unroll
    for (int i = 0; i < 4; i++) {
        int idx = t + i * 256;
        int il  = idx >> 4;
        int c4  = idx & 15;
        float4 qv = *reinterpret_cast<const float4*>(qb + (size_t)(q0 + il) * F_ + c4 * 4);
        *reinterpret_cast<float4*>(Qs + il * 68 + c4 * 4) = qv;
    }

    float o[4][4];
    float m[4], l[4];
    #pragma unroll
    for (int i = 0; i < 4; i++) {
        m[i] = -INFINITY; l[i] = 0.f;
        #pragma unroll
        for (int j = 0; j < 4; j++) o[i][j] = 0.f;
    }
    __syncthreads();

    #pragma unroll 1
    for (int k0t = 0; k0t < W_; k0t += 64) {
        // ---- stage K (transposed -> c-major) and V (row-major) ----
        #pragma unroll
        for (int i = 0; i < 4; i++) {
            int idx = t + i * 256;
            int jl  = idx >> 4;
            int c4  = idx & 15;
            float4 kv = *reinterpret_cast<const float4*>(kb + (size_t)(k0t + jl) * F_ + c4 * 4);
            KP[(c4*4+0)*68 + jl] = kv.x;
            KP[(c4*4+1)*68 + jl] = kv.y;
            KP[(c4*4+2)*68 + jl] = kv.z;
            KP[(c4*4+3)*68 + jl] = kv.w;
            float4 vv = *reinterpret_cast<const float4*>(vb + (size_t)(k0t + jl) * F_ + c4 * 4);
            *reinterpret_cast<float4*>(Vs + jl * 64 + c4 * 4) = vv;
        }
        __syncthreads();

        // ---- S = Q @ K^T (64x64 tile, 4x4 micro, c unrolled by 4) ----
        float s[4][4];
        #pragma unroll
        for (int i = 0; i < 4; i++)
            #pragma unroll
            for (int j = 0; j < 4; j++) s[i][j] = 0.f;
        #pragma unroll 4
        for (int c0 = 0; c0 < 64; c0 += 4) {
            float4 q4[4];
            #pragma unroll
            for (int i = 0; i < 4; i++)
                q4[i] = *reinterpret_cast<const float4*>(Qs + (tq*4 + i) * 68 + c0);
            #pragma unroll
            for (int cc = 0; cc < 4; cc++) {
                float4 k4 = *reinterpret_cast<const float4*>(KP + (c0 + cc) * 68 + tf * 4);
                float kr[4] = {k4.x, k4.y, k4.z, k4.w};
                #pragma unroll
                for (int i = 0; i < 4; i++) {
                    float x = reinterpret_cast<const float*>(&q4[i])[cc];
                    #pragma unroll
                    for (int j = 0; j < 4; j++)
                        s[i][j] = fmaf(x, kr[j], s[i][j]);
                }
            }
        }

        // ---- online softmax (row reductions across 16 tf-lanes) ----
        float p[4][4];
        #pragma unroll
        for (int i = 0; i < 4; i++) {
            float mm = fmaxf(fmaxf(s[i][0], s[i][1]), fmaxf(s[i][2], s[i][3]));
            #pragma unroll
            for (int d = 1; d < 16; d <<= 1)
                mm = fmaxf(mm, __shfl_xor_sync(0xffffffffu, mm, d));
            float mnew = fmaxf(m[i], mm);
            float sc = __expf(m[i] - mnew);   // 0 on first tile (m=-inf)
            m[i] = mnew;
            float ls = 0.f;
            #pragma unroll
            for (int j = 0; j < 4; j++) {
                p[i][j] = __expf(s[i][j] - mnew);
                ls += p[i][j];
            }
            #pragma unroll
            for (int d = 1; d < 16; d <<= 1)
                ls += __shfl_xor_sync(0xffffffffu, ls, d);
            l[i] = l[i] * sc + ls;
            #pragma unroll
            for (int j = 0; j < 4; j++) o[i][j] *= sc;
        }

        __syncthreads();   // done reading KP as K
        // ---- stage P ROW-MAJOR: P[q][k], float4 stores (conflict-free) ----
        #pragma unroll
        for (int i = 0; i < 4; i++) {
            float4 pv = make_float4(p[i][0], p[i][1], p[i][2], p[i][3]);
            *reinterpret_cast<float4*>(KP + (tq*4 + i) * 68 + tf * 4) = pv;
        }
        __syncthreads();

        // ---- O += P @ V (k unrolled by 4, float4 P reads) ----
        #pragma unroll 4
        for (int k0 = 0; k0 < 64; k0 += 4) {
            float4 p4[4];
            #pragma unroll
            for (int i = 0; i < 4; i++)
                p4[i] = *reinterpret_cast<const float4*>(KP + (tq*4 + i) * 68 + k0);
            #pragma unroll
            for (int kk = 0; kk < 4; kk++) {
                float4 v4 = *reinterpret_cast<const float4*>(Vs + (k0 + kk) * 64 + tf * 4);
                float vr[4] = {v4.x, v4.y, v4.z, v4.w};
                #pragma unroll
                for (int i = 0; i < 4; i++) {
                    float x = reinterpret_cast<const float*>(&p4[i])[kk];
                    #pragma unroll
                    for (int j = 0; j < 4; j++)
                        o[i][j] = fmaf(x, vr[j], o[i][j]);
                }
            }
        }
        __syncthreads();   // before next tile overwrites KP/Vs
    }

    // ---- epilogue: normalize and store ----
    #pragma unroll
    for (int i = 0; i < 4; i++) {
        float inv = 1.0f / l[i];
        size_t off = ((size_t)bh * W_ + q0 + tq * 4 + i) * F_ + tf * 4;
        float4 r;
        r.x = o[i][0] * inv; r.y = o[i][1] * inv;
        r.z = o[i][2] * inv; r.w = o[i][3] * inv;
        *reinterpret_cast<float4*>(out + off) = r;
    }
}

// ---------------------------------------------------------------------------
extern "C" void kernel_launch(void* const* d_in, const int* in_sizes, int n_in,
                              void* d_out, int out_size)
{
    const float* X  = (const float*)d_in[0];
    const float* Wq = (const float*)d_in[1];
    const float* bq = (const float*)d_in[2];
    const float* Wk = (const float*)d_in[3];
    const float* bk = (const float*)d_in[4];
    const float* Wv = (const float*)d_in[5];
    const float* bv = (const float*)d_in[6];
    float* out = (float*)d_out;

    cudaFuncSetAttribute(conv_qkv_kernel,
                         cudaFuncAttributeMaxDynamicSharedMemorySize, CONV_SMEM);
    cudaFuncSetAttribute(attn_kernel,
                         cudaFuncAttributeMaxDynamicSharedMemorySize, ATTN_SMEM);

    dim3 cgrid(W_ / 64, B_ * H_);
    conv_qkv_kernel<<<cgrid, 256, CONV_SMEM>>>(X, Wq, bq, Wk, bk, Wv, bv);

    dim3 agrid(W_ / 64, B_ * H_);
    attn_kernel<<<agrid, 256, ATTN_SMEM>>>(out);
}

// round 4
// speedup vs baseline: 1.6996x; 1.6369x over previous
#include <cuda_runtime.h>
#include <cuda_bf16.h>
#include <mma.h>
#include <math.h>
#include <stdint.h>

using namespace nvcuda;

#define B_ 8
#define H_ 128
#define W_ 256
#define C_ 64
#define F_ 64
#define NPIX (B_*H_*W_)

// Scratch (allocation-free rule: __device__ globals)
__device__ float g_q[(size_t)NPIX * F_];
__device__ float g_k[(size_t)NPIX * F_];
__device__ float g_v[(size_t)NPIX * F_];
// Pre-transposed, hi/lo-split weights: [tap][n=192][c=64], n = (q f | k f | v f)
__device__ __nv_bfloat16 g_wt_hi[9 * 192 * 64];
__device__ __nv_bfloat16 g_wt_lo[9 * 192 * 64];

// ---------------------------------------------------------------------------
// Weight prep: transpose + hi/lo bf16 split. Wt[tap][n][c], n = q|k|v x f.
// ---------------------------------------------------------------------------
__global__ void prep_w_kernel(const float* __restrict__ Wq,
                              const float* __restrict__ Wk,
                              const float* __restrict__ Wv)
{
    int idx = blockIdx.x * 256 + threadIdx.x;
    if (idx >= 9 * 192 * 64) return;
    int tap = idx / 12288;
    int r   = idx % 12288;
    int n   = r >> 6;
    int c   = r & 63;
    const float* src = (n < 64) ? Wq : (n < 128) ? Wk : Wv;
    float v = src[tap * 4096 + c * 64 + (n & 63)];
    __nv_bfloat16 h = __float2bfloat16_rn(v);
    g_wt_hi[idx] = h;
    g_wt_lo[idx] = __float2bfloat16_rn(v - __bfloat162float(h));
}

// ---------------------------------------------------------------------------
// wmma bf16 conv: implicit GEMM, M=128 pixels, N=192 (q|k|v), K=576.
// Split-bf16: D += Ah*Bh + Ah*Bl + Al*Bh (fp32 accum in fragments).
// grid (W_/128, B_*H_), 256 threads = 8 warps (4m x 2n).
// ---------------------------------------------------------------------------
#define A_LDM 72                       // halves; 144B row stride (16 mod 128 -> conflict-free)
#define B_LDM 72
#define SM_A_HI 0
#define SM_A_LO (SM_A_HI + 132*A_LDM*2)          // 19008
#define SM_B_HI (SM_A_LO + 132*A_LDM*2)          // 38016
#define SM_B_LO (SM_B_HI + 192*B_LDM*2)          // 65664
#define CONV_SMEM (SM_B_LO + 192*B_LDM*2)        // 93312 B
#define BIAS_LDM 200                              // bias tile lives in B_HI area

__global__ __launch_bounds__(256, 1)
void conv_qkv_wmma_kernel(const float* __restrict__ X,
                          const float* __restrict__ bq,
                          const float* __restrict__ bk,
                          const float* __restrict__ bv)
{
    extern __shared__ char sm[];
    __nv_bfloat16* A_hi = reinterpret_cast<__nv_bfloat16*>(sm + SM_A_HI);
    __nv_bfloat16* A_lo = reinterpret_cast<__nv_bfloat16*>(sm + SM_A_LO);
    __nv_bfloat16* B_hi = reinterpret_cast<__nv_bfloat16*>(sm + SM_B_HI);
    __nv_bfloat16* B_lo = reinterpret_cast<__nv_bfloat16*>(sm + SM_B_LO);
    float* biasT = reinterpret_cast<float*>(sm + SM_B_HI);   // 16 x 200 fp32, transient

    const int t   = threadIdx.x;
    const int wid = t >> 5;
    const int warp_m = wid >> 1;        // 0..3 -> 32 m-rows each
    const int warp_n = wid & 1;         // 0..1 -> 96 n-cols each
    const int bh  = blockIdx.y;
    const int b   = bh / H_;
    const int h   = bh % H_;
    const int w0  = blockIdx.x * 128;

    // ---- build replicated bias tile, init accumulators from it ----
    for (int idx = t; idx < 16 * 192; idx += 256) {
        int row = idx / 192, col = idx % 192;
        float bvv = (col < 64) ? bq[col] : (col < 128) ? bk[col - 64] : bv[col - 128];
        biasT[row * BIAS_LDM + col] = bvv;
    }
    __syncthreads();

    wmma::fragment<wmma::accumulator, 16, 16, 16, float> acc[2][6];
    #pragma unroll
    for (int i = 0; i < 2; i++)
        #pragma unroll
        for (int j = 0; j < 6; j++)
            wmma::load_matrix_sync(acc[i][j], biasT + warp_n * 96 + j * 16,
                                   BIAS_LDM, wmma::mem_row_major);

    // ---- main loop over taps ----
    #pragma unroll 1
    for (int kh = 0; kh < 3; kh++) {
        __syncthreads();    // prev tap MMAs done (and bias reads done at kh=0)

        const int hh = h + (kh - 1) * 2;
        const bool hok = (hh >= 0) && (hh < H_);
        const float* xrow = X + ((size_t)(b * H_ + hh) * W_) * C_;

        // ---- stage A window: 132 rows (w0-2 .. w0+129), hi/lo bf16 ----
        for (int idx = t; idx < 132 * 16; idx += 256) {
            int r  = idx >> 4;
            int c4 = idx & 15;
            int ww = w0 + r - 2;
            float4 xv = make_float4(0.f, 0.f, 0.f, 0.f);
            if (hok && (unsigned)ww < (unsigned)W_)
                xv = *reinterpret_cast<const float4*>(xrow + (size_t)ww * C_ + c4 * 4);
            __nv_bfloat162 h01 = __floats2bfloat162_rn(xv.x, xv.y);
            __nv_bfloat162 h23 = __floats2bfloat162_rn(xv.z, xv.w);
            __nv_bfloat162 l01 = __floats2bfloat162_rn(
                xv.x - __bfloat162float(__low2bfloat16(h01)),
                xv.y - __bfloat162float(__high2bfloat16(h01)));
            __nv_bfloat162 l23 = __floats2bfloat162_rn(
                xv.z - __bfloat162float(__low2bfloat16(h23)),
                xv.w - __bfloat162float(__high2bfloat16(h23)));
            uint2 hv, lv;
            hv.x = *reinterpret_cast<uint32_t*>(&h01);
            hv.y = *reinterpret_cast<uint32_t*>(&h23);
            lv.x = *reinterpret_cast<uint32_t*>(&l01);
            lv.y = *reinterpret_cast<uint32_t*>(&l23);
            *reinterpret_cast<uint2*>(A_hi + r * A_LDM + c4 * 4) = hv;
            *reinterpret_cast<uint2*>(A_lo + r * A_LDM + c4 * 4) = lv;
        }

        #pragma unroll 1
        for (int kw = 0; kw < 3; kw++) {
            if (kw) __syncthreads();   // prev MMA done reading B

            // ---- stage B for this tap: [192 n][64 c] hi/lo ----
            const int tap = kh * 3 + kw;
            const __nv_bfloat16* wh = g_wt_hi + tap * 12288;
            const __nv_bfloat16* wl = g_wt_lo + tap * 12288;
            #pragma unroll
            for (int i = 0; i < 6; i++) {
                int idx = t + i * 256;           // 1536 granules of 8 halves
                int n   = idx >> 3;
                int c8  = idx & 7;
                float4 vh = *reinterpret_cast<const float4*>(wh + n * 64 + c8 * 8);
                float4 vl = *reinterpret_cast<const float4*>(wl + n * 64 + c8 * 8);
                *reinterpret_cast<float4*>(B_hi + n * B_LDM + c8 * 8) = vh;
                *reinterpret_cast<float4*>(B_lo + n * B_LDM + c8 * 8) = vl;
            }
            __syncthreads();

            // ---- MMA: 4 k-steps x (2m x 6n) x 3 splits ----
            const int rbase = warp_m * 32 + kw * 2;   // A window row offset
            #pragma unroll
            for (int ks = 0; ks < 4; ks++) {
                const int c0 = ks * 16;
                wmma::fragment<wmma::matrix_a, 16, 16, 16, __nv_bfloat16, wmma::row_major> ah[2], al[2];
                #pragma unroll
                for (int i = 0; i < 2; i++) {
                    wmma::load_matrix_sync(ah[i], A_hi + (rbase + i * 16) * A_LDM + c0, A_LDM);
                    wmma::load_matrix_sync(al[i], A_lo + (rbase + i * 16) * A_LDM + c0, A_LDM);
                }
                #pragma unroll
                for (int j = 0; j < 6; j++) {
                    wmma::fragment<wmma::matrix_b, 16, 16, 16, __nv_bfloat16, wmma::col_major> bhf, blf;
                    const int n0 = warp_n * 96 + j * 16;
                    wmma::load_matrix_sync(bhf, B_hi + n0 * B_LDM + c0, B_LDM);
                    wmma::load_matrix_sync(blf, B_lo + n0 * B_LDM + c0, B_LDM);
                    #pragma unroll
                    for (int i = 0; i < 2; i++) {
                        wmma::mma_sync(acc[i][j], ah[i], bhf, acc[i][j]);
                        wmma::mma_sync(acc[i][j], ah[i], blf, acc[i][j]);
                        wmma::mma_sync(acc[i][j], al[i], bhf, acc[i][j]);
                    }
                }
            }
        }
    }

    // ---- epilogue: store fragments straight to g_q/g_k/g_v ----
    #pragma unroll
    for (int i = 0; i < 2; i++) {
        const int m0 = warp_m * 32 + i * 16;
        const size_t pix0 = (size_t)bh * W_ + w0 + m0;
        #pragma unroll
        for (int j = 0; j < 6; j++) {
            const int n0 = warp_n * 96 + j * 16;
            float* dst = (n0 < 64) ? g_q : (n0 < 128) ? g_k : g_v;
            wmma::store_matrix_sync(dst + pix0 * 64 + (n0 & 63), acc[i][j],
                                    64, wmma::mem_row_major);
        }
    }
}

// ---------------------------------------------------------------------------
// Flash attention along W per (b,h). grid (W_/64, B_*H_), 256 threads.
// (unchanged from round 2 — fp32 SIMT)
// ---------------------------------------------------------------------------
#define ATTN_SMEM ((64*68 + 64*68 + 64*64) * 4)

__global__ __launch_bounds__(256) void attn_kernel(float* __restrict__ out)
{
    extern __shared__ float smf[];
    float* Qs = smf;
    float* KP = smf + 64 * 68;
    float* Vs = smf + 2 * 64 * 68;

    const int t  = threadIdx.x;
    const int tq = t >> 4;
    const int tf = t & 15;
    const int bh = blockIdx.y;
    const int q0 = blockIdx.x * 64;

    const float* qb = g_q + (size_t)bh * W_ * F_;
    const float* kb = g_k + (size_t)bh * W_ * F_;
    const float* vb = g_v + (size_t)bh * W_ * F_;

    #pragma unroll
    for (int i = 0; i < 4; i++) {
        int idx = t + i * 256;
        int il  = idx >> 4;
        int c4  = idx & 15;
        float4 qv = *reinterpret_cast<const float4*>(qb + (size_t)(q0 + il) * F_ + c4 * 4);
        *reinterpret_cast<float4*>(Qs + il * 68 + c4 * 4) = qv;
    }

    float o[4][4];
    float m[4], l[4];
    #pragma unroll
    for (int i = 0; i < 4; i++) {
        m[i] = -INFINITY; l[i] = 0.f;
        #pragma unroll
        for (int j = 0; j < 4; j++) o[i][j] = 0.f;
    }
    __syncthreads();

    #pragma unroll 1
    for (int k0t = 0; k0t < W_; k0t += 64) {
        #pragma unroll
        for (int i = 0; i < 4; i++) {
            int idx = t + i * 256;
            int jl  = idx >> 4;
            int c4  = idx & 15;
            float4 kv = *reinterpret_cast<const float4*>(kb + (size_t)(k0t + jl) * F_ + c4 * 4);
            KP[(c4*4+0)*68 + jl] = kv.x;
            KP[(c4*4+1)*68 + jl] = kv.y;
            KP[(c4*4+2)*68 + jl] = kv.z;
            KP[(c4*4+3)*68 + jl] = kv.w;
            float4 vv = *reinterpret_cast<const float4*>(vb + (size_t)(k0t + jl) * F_ + c4 * 4);
            *reinterpret_cast<float4*>(Vs + jl * 64 + c4 * 4) = vv;
        }
        __syncthreads();

        float s[4][4];
        #pragma unroll
        for (int i = 0; i < 4; i++)
            #pragma unroll
            for (int j = 0; j < 4; j++) s[i][j] = 0.f;
        #pragma unroll 4
        for (int c0 = 0; c0 < 64; c0 += 4) {
            float4 q4[4];
            #pragma unroll
            for (int i = 0; i < 4; i++)
                q4[i] = *reinterpret_cast<const float4*>(Qs + (tq*4 + i) * 68 + c0);
            #pragma unroll
            for (int cc = 0; cc < 4; cc++) {
                float4 k4 = *reinterpret_cast<const float4*>(KP + (c0 + cc) * 68 + tf * 4);
                float kr[4] = {k4.x, k4.y, k4.z, k4.w};
                #pragma unroll
                for (int i = 0; i < 4; i++) {
                    float x = reinterpret_cast<const float*>(&q4[i])[cc];
                    #pragma unroll
                    for (int j = 0; j < 4; j++)
                        s[i][j] = fmaf(x, kr[j], s[i][j]);
                }
            }
        }

        float p[4][4];
        #pragma unroll
        for (int i = 0; i < 4; i++) {
            float mm = fmaxf(fmaxf(s[i][0], s[i][1]), fmaxf(s[i][2], s[i][3]));
            #pragma unroll
            for (int d = 1; d < 16; d <<= 1)
                mm = fmaxf(mm, __shfl_xor_sync(0xffffffffu, mm, d));
            float mnew = fmaxf(m[i], mm);
            float sc = __expf(m[i] - mnew);
            m[i] = mnew;
            float ls = 0.f;
            #pragma unroll
            for (int j = 0; j < 4; j++) {
                p[i][j] = __expf(s[i][j] - mnew);
                ls += p[i][j];
            }
            #pragma unroll
            for (int d = 1; d < 16; d <<= 1)
                ls += __shfl_xor_sync(0xffffffffu, ls, d);
            l[i] = l[i] * sc + ls;
            #pragma unroll
            for (int j = 0; j < 4; j++) o[i][j] *= sc;
        }

        __syncthreads();
        #pragma unroll
        for (int i = 0; i < 4; i++) {
            float4 pv = make_float4(p[i][0], p[i][1], p[i][2], p[i][3]);
            *reinterpret_cast<float4*>(KP + (tq*4 + i) * 68 + tf * 4) = pv;
        }
        __syncthreads();

        #pragma unroll 4
        for (int k0 = 0; k0 < 64; k0 += 4) {
            float4 p4[4];
            #pragma unroll
            for (int i = 0; i < 4; i++)
                p4[i] = *reinterpret_cast<const float4*>(KP + (tq*4 + i) * 68 + k0);
            #pragma unroll
            for (int kk = 0; kk < 4; kk++) {
                float4 v4 = *reinterpret_cast<const float4*>(Vs + (k0 + kk) * 64 + tf * 4);
                float vr[4] = {v4.x, v4.y, v4.z, v4.w};
                #pragma unroll
                for (int i = 0; i < 4; i++) {
                    float x = reinterpret_cast<const float*>(&p4[i])[kk];
                    #pragma unroll
                    for (int j = 0; j < 4; j++)
                        o[i][j] = fmaf(x, vr[j], o[i][j]);
                }
            }
        }
        __syncthreads();
    }

    #pragma unroll
    for (int i = 0; i < 4; i++) {
        float inv = 1.0f / l[i];
        size_t off = ((size_t)bh * W_ + q0 + tq * 4 + i) * F_ + tf * 4;
        float4 r;
        r.x = o[i][0] * inv; r.y = o[i][1] * inv;
        r.z = o[i][2] * inv; r.w = o[i][3] * inv;
        *reinterpret_cast<float4*>(out + off) = r;
    }
}

// ---------------------------------------------------------------------------
extern "C" void kernel_launch(void* const* d_in, const int* in_sizes, int n_in,
                              void* d_out, int out_size)
{
    const float* X  = (const float*)d_in[0];
    const float* Wq = (const float*)d_in[1];
    const float* bq = (const float*)d_in[2];
    const float* Wk = (const float*)d_in[3];
    const float* bk = (const float*)d_in[4];
    const float* Wv = (const float*)d_in[5];
    const float* bv = (const float*)d_in[6];
    float* out = (float*)d_out;

    cudaFuncSetAttribute(conv_qkv_wmma_kernel,
                         cudaFuncAttributeMaxDynamicSharedMemorySize, CONV_SMEM);
    cudaFuncSetAttribute(attn_kernel,
                         cudaFuncAttributeMaxDynamicSharedMemorySize, ATTN_SMEM);

    prep_w_kernel<<<(9 * 192 * 64 + 255) / 256, 256>>>(Wq, Wk, Wv);

    dim3 cgrid(W_ / 128, B_ * H_);
    conv_qkv_wmma_kernel<<<cgrid, 256, CONV_SMEM>>>(X, bq, bk, bv);

    dim3 agrid(W_ / 64, B_ * H_);
    attn_kernel<<<agrid, 256, ATTN_SMEM>>>(out);
}